// round 15
// baseline (speedup 1.0000x reference)
#include <cuda_runtime.h>
#include <cstdint>

#define BATCH 8
#define NPTS  8192
#define NGRP  512
#define KNN   32
#define NEIGH_ATTR_OFF 393216   /* 8*512*32*3 */
#define CENTER_OFF     786432
#define CATTR_OFF      798720
#define CAP 2048

#define CSZ   4                 /* cluster CTAs per batch */
#define PPC   2048              /* points per CTA */
#define TAGM  0x7FFFFu
#define WTAGM 0x1FFu
#define NFPS  32                /* fps CTAs (8 clusters of 4) */
#define NWORK 100               /* knn worker CTAs */
#define NCTA  132               /* single wave */

__device__ float4   g_center4[BATCH * NGRP];  // {cx,cy,cz, tag=g+1} single-word publish
__device__ float4   g_pts[BATCH * NPTS];      // {x, y, z, (x*x+y*y)+z*z}
__device__ unsigned g_ready[BATCH * CSZ];     // per-rank g_pts ready flags

// ---- packed f32x2 helpers (IEEE rn per lane == scalar FADD/FMUL bitwise) ----
__device__ __forceinline__ unsigned long long f2pack(float lo, float hi) {
    unsigned long long r;
    asm("mov.b64 %0, {%1,%2};" : "=l"(r) : "f"(lo), "f"(hi));
    return r;
}
__device__ __forceinline__ void f2unpack(unsigned long long v, float& lo, float& hi) {
    asm("mov.b64 {%0,%1}, %2;" : "=f"(lo), "=f"(hi) : "l"(v));
}
__device__ __forceinline__ unsigned long long f2add(unsigned long long a, unsigned long long b) {
    unsigned long long r;
    asm("add.rn.f32x2 %0, %1, %2;" : "=l"(r) : "l"(a), "l"(b));
    return r;
}
__device__ __forceinline__ unsigned long long f2mul(unsigned long long a, unsigned long long b) {
    unsigned long long r;
    asm("mul.rn.f32x2 %0, %1, %2;" : "=l"(r) : "l"(a), "l"(b));
    return r;
}

// ---- cluster / DSMEM helpers ----
__device__ __forceinline__ uint32_t smem_u32(const void* p) {
    uint32_t a;
    asm("{ .reg .u64 t; cvta.to.shared.u64 t, %1; cvt.u32.u64 %0, t; }" : "=r"(a) : "l"(p));
    return a;
}
__device__ __forceinline__ uint32_t mapa_u32(uint32_t addr, uint32_t rank) {
    uint32_t r;
    asm("mapa.shared::cluster.u32 %0, %1, %2;" : "=r"(r) : "r"(addr), "r"(rank));
    return r;
}
__device__ __forceinline__ void st_cluster_u64(uint32_t addr, unsigned long long v) {
    asm volatile("st.shared::cluster.u64 [%0], %1;" :: "r"(addr), "l"(v) : "memory");
}
__device__ __forceinline__ unsigned long long ld_vol_u64(uint32_t addr) {
    unsigned long long v;
    asm volatile("ld.volatile.shared.u64 %0, [%1];" : "=l"(v) : "r"(addr) : "memory");
    return v;
}
__device__ __forceinline__ void st_vol_u64(uint32_t addr, unsigned long long v) {
    asm volatile("st.volatile.shared.u64 [%0], %1;" :: "r"(addr), "l"(v) : "memory");
}

// ---------------- fused kernel: 32 FPS CTAs + 100 knn worker CTAs -------------
__global__ __launch_bounds__(512, 1) __cluster_dims__(CSZ, 1, 1)
void fused_kernel(const float* __restrict__ xyz, float* __restrict__ out) {
    extern __shared__ float dyn[];          // fps: 96KB coord planes
    // fps small statics
    __shared__ __align__(16) unsigned long long s_wvt[16];  // tagged warp results
    __shared__ int s_idx[NGRP];
    __shared__ int s_cur;
    __shared__ __align__(16) unsigned long long s_box[2][CSZ];
    // knn worker statics
    __shared__ float s_c[4];
    __shared__ unsigned long long s_min[512];
    __shared__ unsigned long long s_src[64];
    __shared__ unsigned long long s_T;
    __shared__ int s_cnt;
    __shared__ unsigned long long s_cand[CAP];

    const int tid = threadIdx.x;
    const int bid = blockIdx.x;

    if (bid < NFPS) {
        // ================= FPS path =================
        float* sx = dyn;
        float* sy = dyn + NPTS;
        float* sz = dyn + 2 * NPTS;
        const int b    = bid >> 2;
        const int rank = bid & 3;
        const float* base = xyz + (size_t)b * NPTS * 6;
        const int gbase = rank * PPC;

#pragma unroll
        for (int k = 0; k < 16; k++) {
            int p = tid + (k << 9);
            float x = __ldg(base + p * 6 + 0);
            float y = __ldg(base + p * 6 + 1);
            float z = __ldg(base + p * 6 + 2);
            sx[p] = x; sy[p] = y; sz[p] = z;
            if (p >= gbase && p < gbase + PPC) {
                float xn = __fadd_rn(__fadd_rn(__fmul_rn(x, x), __fmul_rn(y, y)),
                                     __fmul_rn(z, z));
                g_pts[b * NPTS + p] = make_float4(x, y, z, xn);
            }
        }
        if (tid < 2 * CSZ) s_box[tid >> 2][tid & 3] = 0ull;   // tag=0
        if (tid < 16) s_wvt[tid] = 0ull;                      // tag=0
        if (tid == 0) s_idx[0] = 0;
        __syncthreads();
        // publish OWN g_pts range: write -> fence -> volatile flag (same CTA)
        if (tid == 0) {
            __threadfence();
            *(volatile unsigned*)&g_ready[b * CSZ + rank] = 1u;
        }
        asm volatile("barrier.cluster.arrive.aligned;" ::: "memory");
        asm volatile("barrier.cluster.wait.aligned;" ::: "memory");

        // publish center 0 (= point 0), tag = 1, single 16B word
        if (rank == 0 && tid == 0) {
            __stcg(&g_center4[b * NGRP],
                   make_float4(sx[0], sy[0], sz[0], __int_as_float(1)));
        }

        float tx[4], ty[4], tz[4], pd[4];
#pragma unroll
        for (int k = 0; k < 4; k++) {
            int g = gbase + tid + (k << 9);
            tx[k] = sx[g]; ty[k] = sy[g]; tz[k] = sz[g]; pd[k] = 1e10f;
        }
        unsigned long long px2[2], py2[2], pz2[2];
#pragma unroll
        for (int j = 0; j < 2; j++) {
            px2[j] = f2pack(tx[2 * j], tx[2 * j + 1]);
            py2[j] = f2pack(ty[2 * j], ty[2 * j + 1]);
            pz2[j] = f2pack(tz[2 * j], tz[2 * j + 1]);
        }

        const uint32_t box_a = smem_u32(&s_box[0][0]);
        const uint32_t wvt_a = smem_u32(&s_wvt[0]);
        const int lane = tid & 31, wid = tid >> 5;

        float cx = __ldg(base + 0), cy = __ldg(base + 1), cz = __ldg(base + 2);

        for (int t = 1; t < NGRP; t++) {
            unsigned long long ncx2 = f2pack(-cx, -cx);
            unsigned long long ncy2 = f2pack(-cy, -cy);
            unsigned long long ncz2 = f2pack(-cz, -cz);
            float bv = -1.0f;
            int bi = 0x7FFFFFFF;
#pragma unroll
            for (int j = 0; j < 2; j++) {
                unsigned long long dx = f2add(px2[j], ncx2);   // x+(-c) == x-c exact
                unsigned long long dy = f2add(py2[j], ncy2);
                unsigned long long dz = f2add(pz2[j], ncz2);
                unsigned long long s = f2add(f2add(f2mul(dx, dx), f2mul(dy, dy)),
                                             f2mul(dz, dz));
                float dlo, dhi;
                f2unpack(s, dlo, dhi);
                float n0 = fminf(pd[2 * j], dlo);
                pd[2 * j] = n0;
                if (n0 > bv) { bv = n0; bi = tid + ((2 * j) << 9); }
                float n1 = fminf(pd[2 * j + 1], dhi);
                pd[2 * j + 1] = n1;
                if (n1 > bv) { bv = n1; bi = tid + ((2 * j + 1) << 9); }
            }
            unsigned vb = __float_as_uint(bv);
            unsigned vmax = __reduce_max_sync(0xFFFFFFFFu, vb);
            int cand = (vb == vmax) ? bi : 0x7FFFFFFF;
            int imin = __reduce_min_sync(0xFFFFFFFFu, cand);   // 0..2047 local
            const unsigned wtag = (unsigned)t & WTAGM;
            if (lane == 0)
                st_vol_u64(wvt_a + (unsigned)wid * 8u,
                           ((unsigned long long)vmax << 32)
                         | ((unsigned long long)(unsigned)imin << 9)
                         | (unsigned long long)wtag);

            const int buf = t & 1;
            const unsigned tag = (unsigned)t & TAGM;
            if (wid == 0) {
                // spin until all 16 warp words carry this iteration's tag
                const uint32_t wa = wvt_a + (unsigned)(lane & 15) * 8u;
                unsigned long long w;
                for (;;) {
                    w = ld_vol_u64(wa);
                    if (__all_sync(0xFFFFFFFFu, ((unsigned)w & WTAGM) == wtag)) break;
                }
                unsigned vmax_l = (unsigned)(w >> 32);
                int imin_l = (int)((w >> 9) & 0x7FFull);
                unsigned v2 = (lane < 16) ? vmax_l : 0u;
                unsigned m2 = __reduce_max_sync(0xFFFFFFFFu, v2);
                int c2 = (lane < 16 && v2 == m2) ? imin_l : 0x7FFFFFFF;
                int lbest = __reduce_min_sync(0xFFFFFFFFu, c2);
                unsigned gidx = (unsigned)(gbase + lbest);
                unsigned long long key = ((unsigned long long)m2 << 32)
                                       | ((unsigned long long)(8191u - gidx) << 19)
                                       | (unsigned long long)tag;
                if (lane < CSZ) {
                    uint32_t dst = mapa_u32(box_a + (unsigned)(buf * CSZ + rank) * 8u,
                                            (uint32_t)lane);
                    st_cluster_u64(dst, key);   // 4 lanes deliver in parallel
                }
                // parallel poll: lane i watches slot i&3
                const uint32_t pa = box_a + (unsigned)(buf * CSZ + (lane & 3)) * 8u;
                unsigned long long bk;
                for (;;) {
                    bk = ld_vol_u64(pa);
                    if (__all_sync(0xFFFFFFFFu, ((unsigned)bk & TAGM) == tag)) break;
                }
#pragma unroll
                for (int off = 1; off < 4; off <<= 1) {
                    unsigned long long o = __shfl_xor_sync(0xFFFFFFFFu, bk, off);
                    if (o > bk) bk = o;
                }
                int widx = 8191 - (int)((bk >> 19) & 0x1FFFull);
                if (lane == 0) {
                    s_cur = widx;
                    if (rank == 0) s_idx[t] = widx;
                }
                if (rank == 0 && lane == 1) {
                    // publish center t: ONE 16B word {x,y,z,tag=t+1} — data==flag
                    __stcg(&g_center4[b * NGRP + t],
                           make_float4(sx[widx], sy[widx], sz[widx],
                                       __int_as_float(t + 1)));
                }
            }
            __syncthreads();   // single barrier per iteration
            int cur = s_cur;
            cx = sx[cur]; cy = sy[cur]; cz = sz[cur];
        }

        if (rank == 0 && tid < NGRP) {
            int idx = s_idx[tid];
            int go = b * NGRP + tid;
            out[CENTER_OFF + go * 3 + 0] = sx[idx];
            out[CENTER_OFF + go * 3 + 1] = sy[idx];
            out[CENTER_OFF + go * 3 + 2] = sz[idx];
            const float* ap = base + idx * 6 + 3;
            out[CATTR_OFF + go * 3 + 0] = __ldg(ap + 0);
            out[CATTR_OFF + go * 3 + 1] = __ldg(ap + 1);
            out[CATTR_OFF + go * 3 + 2] = __ldg(ap + 2);
        }
        asm volatile("barrier.cluster.arrive.aligned;" ::: "memory");
        asm volatile("barrier.cluster.wait.aligned;" ::: "memory");

    } else {
        // ================= knn worker path (proven R14 body) ===============
        if (tid < BATCH * CSZ) {
            while (*(volatile unsigned*)&g_ready[tid] == 0u) __nanosleep(128);
        }
        __threadfence();
        __syncthreads();

        const int w = bid - NFPS;
        for (int task = w; task < BATCH * NGRP; task += NWORK) {
            const int g = task >> 3;       // group index 0..511 (ascending per worker)
            const int b = task & 7;        // batch
            const int bg = b * NGRP + g;

            if (tid == 0) {
                float4 c;
                for (;;) {
                    c = __ldcv(&g_center4[bg]);
                    if (__float_as_int(c.w) == g + 1) break;
                    __nanosleep(64);
                }
                s_c[0] = c.x; s_c[1] = c.y; s_c[2] = c.z;
                s_c[3] = __fadd_rn(__fadd_rn(__fmul_rn(c.x, c.x), __fmul_rn(c.y, c.y)),
                                   __fmul_rn(c.z, c.z));
                s_cnt = 0;
            }
            __syncthreads();
            const float cx = s_c[0], cy = s_c[1], cz = s_c[2], cn = s_c[3];
            const float4* pts = g_pts + (size_t)b * NPTS;   // plain loads (no __ldg)

            unsigned keys[16];
            unsigned long long mn = ~0ull;
#pragma unroll
            for (int k = 0; k < 16; k++) {
                int p = tid + (k << 9);
                float4 q = pts[p];
                float dt = __fmaf_rn(cz, q.z, __fmaf_rn(cy, q.y, __fmul_rn(cx, q.x)));
                float d2 = __fadd_rn(__fsub_rn(cn, __fmul_rn(2.0f, dt)), q.w);
                unsigned u = __float_as_uint(d2);
                unsigned key = u ^ ((unsigned)((int)u >> 31) | 0x80000000u);
                keys[k] = key;
                unsigned long long pk = ((unsigned long long)key << 32) | (unsigned)p;
                if (pk < mn) mn = pk;
            }
            s_min[tid] = mn;
            __syncthreads();

            if (tid < 64) {
                unsigned long long a = s_min[8 * tid];
#pragma unroll
                for (int i = 1; i < 8; i++) {
                    unsigned long long v = s_min[8 * tid + i];
                    if (v < a) a = v;
                }
                s_src[tid] = a;
            }
            __syncthreads();
            if (tid < 64) {
                unsigned long long m = s_src[tid];
                int r = 0;
                for (int j = 0; j < 64; j++) r += (s_src[j] < m) ? 1 : 0;
                if (r == 31) s_T = m;
            }
            __syncthreads();
            const unsigned long long T = s_T;

#pragma unroll
            for (int k = 0; k < 16; k++) {
                unsigned long long pk =
                    ((unsigned long long)keys[k] << 32) | (unsigned)(tid + (k << 9));
                if (pk <= T) {
                    int pos = atomicAdd(&s_cnt, 1);
                    if (pos < CAP) s_cand[pos] = pk;
                }
            }
            __syncthreads();

            int n = s_cnt;
            if (n > CAP) n = CAP;
            for (int c = tid; c < n; c += 512) {
                unsigned long long pk = s_cand[c];
                int r = 0;
                for (int j = 0; j < n; j++) r += (s_cand[j] < pk) ? 1 : 0;
                if (r < KNN) {
                    int p = (int)(pk & 0xFFFFFFFFull);
                    const float* pp = xyz + ((size_t)b * NPTS + p) * 6;
                    size_t o = ((size_t)bg * KNN + r) * 3;
                    out[o + 0] = __fsub_rn(__ldg(pp + 0), cx);
                    out[o + 1] = __fsub_rn(__ldg(pp + 1), cy);
                    out[o + 2] = __fsub_rn(__ldg(pp + 2), cz);
                    out[NEIGH_ATTR_OFF + o + 0] = __ldg(pp + 3);
                    out[NEIGH_ATTR_OFF + o + 1] = __ldg(pp + 4);
                    out[NEIGH_ATTR_OFF + o + 2] = __ldg(pp + 5);
                }
            }
            __syncthreads();   // s_cand/s_cnt reuse next task
        }
    }
}

extern "C" void kernel_launch(void* const* d_in, const int* in_sizes, int n_in,
                              void* d_out, int out_size) {
    const float* xyz = (const float*)d_in[0];
    float* out = (float*)d_out;
    (void)in_sizes; (void)n_in; (void)out_size;

    const int smem = 3 * NPTS * (int)sizeof(float);   // 96 KB coord planes
    cudaFuncSetAttribute(fused_kernel, cudaFuncAttributeMaxDynamicSharedMemorySize, smem);
    fused_kernel<<<NCTA, 512, smem>>>(xyz, out);
}

// round 16
// speedup vs baseline: 1.0313x; 1.0313x over previous
#include <cuda_runtime.h>
#include <cstdint>

#define BATCH 8
#define NPTS  8192
#define NGRP  512
#define KNN   32
#define NEIGH_ATTR_OFF 393216   /* 8*512*32*3 */
#define CENTER_OFF     786432
#define CATTR_OFF      798720
#define CAP 2048

#define CSZ   4                 /* cluster CTAs per batch */
#define PPC   2048              /* points per CTA */
#define TAGM  0x7FFFFu
#define NFPS  32                /* fps CTAs (8 clusters of 4) */
#define NWORK 100               /* knn worker CTAs */
#define NCTA  132               /* = CTAS_ACTIVE at cluster_size=4 -> single wave */

__device__ float4   g_center4[BATCH * NGRP];  // {cx,cy,cz, tag=g+1} single-word publish
__device__ float4   g_pts[BATCH * NPTS];      // {x, y, z, (x*x+y*y)+z*z}
__device__ unsigned g_ready[BATCH * CSZ];     // per-rank g_pts ready flags

// ---- packed f32x2 helpers (IEEE rn per lane == scalar FADD/FMUL bitwise) ----
__device__ __forceinline__ unsigned long long f2pack(float lo, float hi) {
    unsigned long long r;
    asm("mov.b64 %0, {%1,%2};" : "=l"(r) : "f"(lo), "f"(hi));
    return r;
}
__device__ __forceinline__ void f2unpack(unsigned long long v, float& lo, float& hi) {
    asm("mov.b64 {%0,%1}, %2;" : "=f"(lo), "=f"(hi) : "l"(v));
}
__device__ __forceinline__ unsigned long long f2add(unsigned long long a, unsigned long long b) {
    unsigned long long r;
    asm("add.rn.f32x2 %0, %1, %2;" : "=l"(r) : "l"(a), "l"(b));
    return r;
}
__device__ __forceinline__ unsigned long long f2mul(unsigned long long a, unsigned long long b) {
    unsigned long long r;
    asm("mul.rn.f32x2 %0, %1, %2;" : "=l"(r) : "l"(a), "l"(b));
    return r;
}

// ---- cluster / DSMEM helpers ----
__device__ __forceinline__ uint32_t smem_u32(const void* p) {
    uint32_t a;
    asm("{ .reg .u64 t; cvta.to.shared.u64 t, %1; cvt.u32.u64 %0, t; }" : "=r"(a) : "l"(p));
    return a;
}
__device__ __forceinline__ uint32_t mapa_u32(uint32_t addr, uint32_t rank) {
    uint32_t r;
    asm("mapa.shared::cluster.u32 %0, %1, %2;" : "=r"(r) : "r"(addr), "r"(rank));
    return r;
}
__device__ __forceinline__ void st_cluster_u64(uint32_t addr, unsigned long long v) {
    asm volatile("st.shared::cluster.u64 [%0], %1;" :: "r"(addr), "l"(v) : "memory");
}
__device__ __forceinline__ unsigned long long ld_vol_u64(uint32_t addr) {
    unsigned long long v;
    asm volatile("ld.volatile.shared.u64 %0, [%1];" : "=l"(v) : "r"(addr) : "memory");
    return v;
}

// ---------------- fused kernel: 32 FPS CTAs + 100 knn worker CTAs -------------
__global__ __launch_bounds__(512, 1) __cluster_dims__(CSZ, 1, 1)
void fused_kernel(const float* __restrict__ xyz, float* __restrict__ out) {
    extern __shared__ float dyn[];          // fps: 96KB coord planes
    // fps small statics
    __shared__ unsigned s_wv[16];
    __shared__ int s_wi[16];
    __shared__ int s_idx[NGRP];
    __shared__ int s_cur;
    __shared__ __align__(16) unsigned long long s_box[2][CSZ];
    // knn worker statics
    __shared__ float s_c[4];
    __shared__ unsigned long long s_min[512];
    __shared__ unsigned long long s_src[64];
    __shared__ unsigned long long s_T;
    __shared__ int s_cnt;
    __shared__ unsigned long long s_cand[CAP];

    const int tid = threadIdx.x;
    const int bid = blockIdx.x;

    if (bid < NFPS) {
        // ================= FPS path (proven R14 structure) ================
        float* sx = dyn;
        float* sy = dyn + NPTS;
        float* sz = dyn + 2 * NPTS;
        const int b    = bid >> 2;
        const int rank = bid & 3;
        const float* base = xyz + (size_t)b * NPTS * 6;
        const int gbase = rank * PPC;

#pragma unroll
        for (int k = 0; k < 16; k++) {
            int p = tid + (k << 9);
            float x = __ldg(base + p * 6 + 0);
            float y = __ldg(base + p * 6 + 1);
            float z = __ldg(base + p * 6 + 2);
            sx[p] = x; sy[p] = y; sz[p] = z;
            if (p >= gbase && p < gbase + PPC) {
                float xn = __fadd_rn(__fadd_rn(__fmul_rn(x, x), __fmul_rn(y, y)),
                                     __fmul_rn(z, z));
                g_pts[b * NPTS + p] = make_float4(x, y, z, xn);
            }
        }
        if (tid < 2 * CSZ) s_box[tid >> 2][tid & 3] = 0ull;   // tag=0
        if (tid == 0) s_idx[0] = 0;
        __syncthreads();
        // publish OWN g_pts range: write -> fence -> volatile flag (same CTA)
        if (tid == 0) {
            __threadfence();
            *(volatile unsigned*)&g_ready[b * CSZ + rank] = 1u;
        }
        asm volatile("barrier.cluster.arrive.aligned;" ::: "memory");
        asm volatile("barrier.cluster.wait.aligned;" ::: "memory");

        // publish center 0 (= point 0), tag = 1, single 16B word
        if (rank == 0 && tid == 0) {
            __stcg(&g_center4[b * NGRP],
                   make_float4(sx[0], sy[0], sz[0], __int_as_float(1)));
        }

        float tx[4], ty[4], tz[4], pd[4];
#pragma unroll
        for (int k = 0; k < 4; k++) {
            int g = gbase + tid + (k << 9);
            tx[k] = sx[g]; ty[k] = sy[g]; tz[k] = sz[g]; pd[k] = 1e10f;
        }
        unsigned long long px2[2], py2[2], pz2[2];
#pragma unroll
        for (int j = 0; j < 2; j++) {
            px2[j] = f2pack(tx[2 * j], tx[2 * j + 1]);
            py2[j] = f2pack(ty[2 * j], ty[2 * j + 1]);
            pz2[j] = f2pack(tz[2 * j], tz[2 * j + 1]);
        }

        const uint32_t box_a = smem_u32(&s_box[0][0]);
        const int lane = tid & 31, wid = tid >> 5;

        float cx = __ldg(base + 0), cy = __ldg(base + 1), cz = __ldg(base + 2);

        for (int t = 1; t < NGRP; t++) {
            unsigned long long ncx2 = f2pack(-cx, -cx);
            unsigned long long ncy2 = f2pack(-cy, -cy);
            unsigned long long ncz2 = f2pack(-cz, -cz);
            float bv = -1.0f;
            int bi = 0x7FFFFFFF;
#pragma unroll
            for (int j = 0; j < 2; j++) {
                unsigned long long dx = f2add(px2[j], ncx2);   // x+(-c) == x-c exact
                unsigned long long dy = f2add(py2[j], ncy2);
                unsigned long long dz = f2add(pz2[j], ncz2);
                unsigned long long s = f2add(f2add(f2mul(dx, dx), f2mul(dy, dy)),
                                             f2mul(dz, dz));
                float dlo, dhi;
                f2unpack(s, dlo, dhi);
                float n0 = fminf(pd[2 * j], dlo);
                pd[2 * j] = n0;
                if (n0 > bv) { bv = n0; bi = tid + ((2 * j) << 9); }
                float n1 = fminf(pd[2 * j + 1], dhi);
                pd[2 * j + 1] = n1;
                if (n1 > bv) { bv = n1; bi = tid + ((2 * j + 1) << 9); }
            }
            unsigned vb = __float_as_uint(bv);
            unsigned vmax = __reduce_max_sync(0xFFFFFFFFu, vb);
            int cand = (vb == vmax) ? bi : 0x7FFFFFFF;
            int imin = __reduce_min_sync(0xFFFFFFFFu, cand);
            if (lane == 0) { s_wv[wid] = vmax; s_wi[wid] = imin; }
            __syncthreads();

            const int buf = t & 1;
            const unsigned tag = (unsigned)t & TAGM;
            if (wid == 0) {
                unsigned v2 = (lane < 16) ? s_wv[lane] : 0u;
                unsigned m2 = __reduce_max_sync(0xFFFFFFFFu, v2);
                int c2 = (lane < 16 && v2 == m2) ? s_wi[lane] : 0x7FFFFFFF;
                int lbest = __reduce_min_sync(0xFFFFFFFFu, c2);
                unsigned gidx = (unsigned)(gbase + lbest);
                unsigned long long key = ((unsigned long long)m2 << 32)
                                       | ((unsigned long long)(8191u - gidx) << 19)
                                       | (unsigned long long)tag;
                if (lane < CSZ) {
                    uint32_t dst = mapa_u32(box_a + (unsigned)(buf * CSZ + rank) * 8u,
                                            (uint32_t)lane);
                    st_cluster_u64(dst, key);   // 4 lanes deliver in parallel
                }
                if (lane == 0) {
                    const uint32_t pa = box_a + (unsigned)(buf * CSZ) * 8u;
                    unsigned long long k0, k1, k2, k3;
                    for (;;) {
                        k0 = ld_vol_u64(pa);
                        k1 = ld_vol_u64(pa + 8u);
                        k2 = ld_vol_u64(pa + 16u);
                        k3 = ld_vol_u64(pa + 24u);
                        if (((unsigned)k0 & TAGM) == tag && ((unsigned)k1 & TAGM) == tag &&
                            ((unsigned)k2 & TAGM) == tag && ((unsigned)k3 & TAGM) == tag)
                            break;
                    }
                    unsigned long long bk = k0;
                    if (k1 > bk) bk = k1;
                    if (k2 > bk) bk = k2;
                    if (k3 > bk) bk = k3;
                    int widx = 8191 - (int)((bk >> 19) & 0x1FFFull);
                    s_cur = widx;
                    if (rank == 0) s_idx[t] = widx;
                }
            }
            __syncthreads();
            int cur = s_cur;
            // publish center t AFTER the barrier, from warp 2 — off warp0's
            // critical path. One 16B word {x,y,z,tag=t+1}: data==flag, no fence.
            if (rank == 0 && tid == 64) {
                __stcg(&g_center4[b * NGRP + t],
                       make_float4(sx[cur], sy[cur], sz[cur],
                                   __int_as_float(t + 1)));
            }
            cx = sx[cur]; cy = sy[cur]; cz = sz[cur];
        }

        if (rank == 0 && tid < NGRP) {
            int idx = s_idx[tid];
            int go = b * NGRP + tid;
            out[CENTER_OFF + go * 3 + 0] = sx[idx];
            out[CENTER_OFF + go * 3 + 1] = sy[idx];
            out[CENTER_OFF + go * 3 + 2] = sz[idx];
            const float* ap = base + idx * 6 + 3;
            out[CATTR_OFF + go * 3 + 0] = __ldg(ap + 0);
            out[CATTR_OFF + go * 3 + 1] = __ldg(ap + 1);
            out[CATTR_OFF + go * 3 + 2] = __ldg(ap + 2);
        }
        asm volatile("barrier.cluster.arrive.aligned;" ::: "memory");
        asm volatile("barrier.cluster.wait.aligned;" ::: "memory");

    } else {
        // ================= knn worker path (proven R14 body) ===============
        // wait once for all 32 per-rank g_pts flags (direct writer->reader order)
        if (tid < BATCH * CSZ) {
            while (*(volatile unsigned*)&g_ready[tid] == 0u) __nanosleep(512);
        }
        __threadfence();
        __syncthreads();

        const int w = bid - NFPS;
        for (int task = w; task < BATCH * NGRP; task += NWORK) {
            const int g = task >> 3;       // group index 0..511 (ascending per worker)
            const int b = task & 7;        // batch
            const int bg = b * NGRP + g;

            if (tid == 0) {
                float4 c;
                for (;;) {
                    c = __ldcv(&g_center4[bg]);
                    if (__float_as_int(c.w) == g + 1) break;
                    __nanosleep(256);
                }
                s_c[0] = c.x; s_c[1] = c.y; s_c[2] = c.z;
                s_c[3] = __fadd_rn(__fadd_rn(__fmul_rn(c.x, c.x), __fmul_rn(c.y, c.y)),
                                   __fmul_rn(c.z, c.z));
                s_cnt = 0;
            }
            __syncthreads();
            const float cx = s_c[0], cy = s_c[1], cz = s_c[2], cn = s_c[3];
            const float4* pts = g_pts + (size_t)b * NPTS;   // plain loads (no __ldg)

            unsigned keys[16];
            unsigned long long mn = ~0ull;
#pragma unroll
            for (int k = 0; k < 16; k++) {
                int p = tid + (k << 9);
                float4 q = pts[p];
                float dt = __fmaf_rn(cz, q.z, __fmaf_rn(cy, q.y, __fmul_rn(cx, q.x)));
                float d2 = __fadd_rn(__fsub_rn(cn, __fmul_rn(2.0f, dt)), q.w);
                unsigned u = __float_as_uint(d2);
                unsigned key = u ^ ((unsigned)((int)u >> 31) | 0x80000000u);
                keys[k] = key;
                unsigned long long pk = ((unsigned long long)key << 32) | (unsigned)p;
                if (pk < mn) mn = pk;
            }
            s_min[tid] = mn;
            __syncthreads();

            if (tid < 64) {
                unsigned long long a = s_min[8 * tid];
#pragma unroll
                for (int i = 1; i < 8; i++) {
                    unsigned long long v = s_min[8 * tid + i];
                    if (v < a) a = v;
                }
                s_src[tid] = a;
            }
            __syncthreads();
            if (tid < 64) {
                unsigned long long m = s_src[tid];
                int r = 0;
                for (int j = 0; j < 64; j++) r += (s_src[j] < m) ? 1 : 0;
                if (r == 31) s_T = m;
            }
            __syncthreads();
            const unsigned long long T = s_T;

#pragma unroll
            for (int k = 0; k < 16; k++) {
                unsigned long long pk =
                    ((unsigned long long)keys[k] << 32) | (unsigned)(tid + (k << 9));
                if (pk <= T) {
                    int pos = atomicAdd(&s_cnt, 1);
                    if (pos < CAP) s_cand[pos] = pk;
                }
            }
            __syncthreads();

            int n = s_cnt;
            if (n > CAP) n = CAP;
            for (int c = tid; c < n; c += 512) {
                unsigned long long pk = s_cand[c];
                int r = 0;
                for (int j = 0; j < n; j++) r += (s_cand[j] < pk) ? 1 : 0;
                if (r < KNN) {
                    int p = (int)(pk & 0xFFFFFFFFull);
                    const float* pp = xyz + ((size_t)b * NPTS + p) * 6;
                    size_t o = ((size_t)bg * KNN + r) * 3;
                    out[o + 0] = __fsub_rn(__ldg(pp + 0), cx);
                    out[o + 1] = __fsub_rn(__ldg(pp + 1), cy);
                    out[o + 2] = __fsub_rn(__ldg(pp + 2), cz);
                    out[NEIGH_ATTR_OFF + o + 0] = __ldg(pp + 3);
                    out[NEIGH_ATTR_OFF + o + 1] = __ldg(pp + 4);
                    out[NEIGH_ATTR_OFF + o + 2] = __ldg(pp + 5);
                }
            }
            __syncthreads();   // s_cand/s_cnt reuse next task
        }
    }
}

extern "C" void kernel_launch(void* const* d_in, const int* in_sizes, int n_in,
                              void* d_out, int out_size) {
    const float* xyz = (const float*)d_in[0];
    float* out = (float*)d_out;
    (void)in_sizes; (void)n_in; (void)out_size;

    const int smem = 3 * NPTS * (int)sizeof(float);   // 96 KB coord planes
    cudaFuncSetAttribute(fused_kernel, cudaFuncAttributeMaxDynamicSharedMemorySize, smem);
    fused_kernel<<<NCTA, 512, smem>>>(xyz, out);
}

// round 17
// speedup vs baseline: 1.0486x; 1.0168x over previous
#include <cuda_runtime.h>
#include <cstdint>

#define BATCH 8
#define NPTS  8192
#define NGRP  512
#define KNN   32
#define NEIGH_ATTR_OFF 393216   /* 8*512*32*3 */
#define CENTER_OFF     786432
#define CATTR_OFF      798720
#define CAP 2048

#define CSZ   4                 /* cluster CTAs per batch */
#define PPC   2048              /* points per CTA */
#define TAGM  0x7FFFFu
#define NFPS  32                /* fps CTAs (8 clusters of 4) */
#define NWORK 100               /* knn worker CTAs */
#define NCTA  132               /* = CTAS_ACTIVE at cluster_size=4 -> single wave */

__device__ float4   g_center4[BATCH * NGRP];  // {cx,cy,cz, tag=g+1} single-word publish
__device__ float4   g_pts[BATCH * NPTS];      // {x, y, z, (x*x+y*y)+z*z}
__device__ unsigned g_ready[BATCH * CSZ];     // per-rank g_pts ready flags

// ---- packed f32x2 helpers (IEEE rn per lane == scalar FADD/FMUL bitwise) ----
__device__ __forceinline__ unsigned long long f2pack(float lo, float hi) {
    unsigned long long r;
    asm("mov.b64 %0, {%1,%2};" : "=l"(r) : "f"(lo), "f"(hi));
    return r;
}
__device__ __forceinline__ void f2unpack(unsigned long long v, float& lo, float& hi) {
    asm("mov.b64 {%0,%1}, %2;" : "=f"(lo), "=f"(hi) : "l"(v));
}
__device__ __forceinline__ unsigned long long f2add(unsigned long long a, unsigned long long b) {
    unsigned long long r;
    asm("add.rn.f32x2 %0, %1, %2;" : "=l"(r) : "l"(a), "l"(b));
    return r;
}
__device__ __forceinline__ unsigned long long f2mul(unsigned long long a, unsigned long long b) {
    unsigned long long r;
    asm("mul.rn.f32x2 %0, %1, %2;" : "=l"(r) : "l"(a), "l"(b));
    return r;
}

// ---- cluster / DSMEM helpers ----
__device__ __forceinline__ uint32_t smem_u32(const void* p) {
    uint32_t a;
    asm("{ .reg .u64 t; cvta.to.shared.u64 t, %1; cvt.u32.u64 %0, t; }" : "=r"(a) : "l"(p));
    return a;
}
__device__ __forceinline__ uint32_t mapa_u32(uint32_t addr, uint32_t rank) {
    uint32_t r;
    asm("mapa.shared::cluster.u32 %0, %1, %2;" : "=r"(r) : "r"(addr), "r"(rank));
    return r;
}
__device__ __forceinline__ void st_cluster_u64(uint32_t addr, unsigned long long v) {
    asm volatile("st.shared::cluster.u64 [%0], %1;" :: "r"(addr), "l"(v) : "memory");
}
__device__ __forceinline__ unsigned long long ld_vol_u64(uint32_t addr) {
    unsigned long long v;
    asm volatile("ld.volatile.shared.u64 %0, [%1];" : "=l"(v) : "r"(addr) : "memory");
    return v;
}

// ---------------- fused kernel: 32 FPS CTAs + 100 knn worker CTAs -------------
__global__ __launch_bounds__(512, 1) __cluster_dims__(CSZ, 1, 1)
void fused_kernel(const float* __restrict__ xyz, float* __restrict__ out) {
    extern __shared__ float4 s_pts4[];      // fps: [NPTS] {x,y,z,xn} = 128 KB
    // fps small statics
    __shared__ __align__(16) unsigned long long s_wk[16];  // vmax<<32 | (2047-imin)
    __shared__ int s_idx[NGRP];
    __shared__ int s_cur;
    __shared__ __align__(16) unsigned long long s_box[2][CSZ];
    // knn worker statics
    __shared__ float s_c[4];
    __shared__ unsigned long long s_min[512];
    __shared__ unsigned long long s_src[64];
    __shared__ unsigned long long s_T;
    __shared__ int s_cnt;
    __shared__ unsigned long long s_cand[CAP];

    const int tid = threadIdx.x;
    const int bid = blockIdx.x;

    if (bid < NFPS) {
        // ================= FPS path (R16 structure; float4 plane + packed keys)
        const int b    = bid >> 2;
        const int rank = bid & 3;
        const float* base = xyz + (size_t)b * NPTS * 6;
        const int gbase = rank * PPC;

#pragma unroll
        for (int k = 0; k < 16; k++) {
            int p = tid + (k << 9);
            float x = __ldg(base + p * 6 + 0);
            float y = __ldg(base + p * 6 + 1);
            float z = __ldg(base + p * 6 + 2);
            float xn = __fadd_rn(__fadd_rn(__fmul_rn(x, x), __fmul_rn(y, y)),
                                 __fmul_rn(z, z));
            float4 v = make_float4(x, y, z, xn);
            s_pts4[p] = v;
            if (p >= gbase && p < gbase + PPC) g_pts[b * NPTS + p] = v;
        }
        if (tid < 2 * CSZ) s_box[tid >> 2][tid & 3] = 0ull;   // tag=0
        if (tid == 0) s_idx[0] = 0;
        __syncthreads();
        // publish OWN g_pts range: write -> fence -> volatile flag (same CTA)
        if (tid == 0) {
            __threadfence();
            *(volatile unsigned*)&g_ready[b * CSZ + rank] = 1u;
        }
        asm volatile("barrier.cluster.arrive.aligned;" ::: "memory");
        asm volatile("barrier.cluster.wait.aligned;" ::: "memory");

        // publish center 0 (= point 0), tag = 1, single 16B word
        if (rank == 0 && tid == 0) {
            float4 p0 = s_pts4[0];
            __stcg(&g_center4[b * NGRP],
                   make_float4(p0.x, p0.y, p0.z, __int_as_float(1)));
        }

        float tx[4], ty[4], tz[4], pd[4];
#pragma unroll
        for (int k = 0; k < 4; k++) {
            float4 q = s_pts4[gbase + tid + (k << 9)];
            tx[k] = q.x; ty[k] = q.y; tz[k] = q.z; pd[k] = 1e10f;
        }
        unsigned long long px2[2], py2[2], pz2[2];
#pragma unroll
        for (int j = 0; j < 2; j++) {
            px2[j] = f2pack(tx[2 * j], tx[2 * j + 1]);
            py2[j] = f2pack(ty[2 * j], ty[2 * j + 1]);
            pz2[j] = f2pack(tz[2 * j], tz[2 * j + 1]);
        }

        const uint32_t box_a = smem_u32(&s_box[0][0]);
        const int lane = tid & 31, wid = tid >> 5;

        float cx = __ldg(base + 0), cy = __ldg(base + 1), cz = __ldg(base + 2);

        for (int t = 1; t < NGRP; t++) {
            unsigned long long ncx2 = f2pack(-cx, -cx);
            unsigned long long ncy2 = f2pack(-cy, -cy);
            unsigned long long ncz2 = f2pack(-cz, -cz);
            float bv = -1.0f;
            int bi = 0x7FFFFFFF;
#pragma unroll
            for (int j = 0; j < 2; j++) {
                unsigned long long dx = f2add(px2[j], ncx2);   // x+(-c) == x-c exact
                unsigned long long dy = f2add(py2[j], ncy2);
                unsigned long long dz = f2add(pz2[j], ncz2);
                unsigned long long s = f2add(f2add(f2mul(dx, dx), f2mul(dy, dy)),
                                             f2mul(dz, dz));
                float dlo, dhi;
                f2unpack(s, dlo, dhi);
                float n0 = fminf(pd[2 * j], dlo);
                pd[2 * j] = n0;
                if (n0 > bv) { bv = n0; bi = tid + ((2 * j) << 9); }
                float n1 = fminf(pd[2 * j + 1], dhi);
                pd[2 * j + 1] = n1;
                if (n1 > bv) { bv = n1; bi = tid + ((2 * j + 1) << 9); }
            }
            unsigned vb = __float_as_uint(bv);
            unsigned vmax = __reduce_max_sync(0xFFFFFFFFu, vb);
            int cand = (vb == vmax) ? bi : 0x7FFFFFFF;
            int imin = __reduce_min_sync(0xFFFFFFFFu, cand);   // 0..2047
            if (lane == 0)
                s_wk[wid] = ((unsigned long long)vmax << 32)
                          | (unsigned long long)(2047u - (unsigned)imin);
            __syncthreads();

            const int buf = t & 1;
            const unsigned tag = (unsigned)t & TAGM;
            if (wid == 0) {
                unsigned long long wkey = (lane < 16) ? s_wk[lane] : 0ull;
                unsigned v2 = (unsigned)(wkey >> 32);
                unsigned m2 = __reduce_max_sync(0xFFFFFFFFu, v2);
                unsigned c2 = (v2 == m2) ? (unsigned)wkey : 0u;   // 2047-imin
                unsigned l2 = __reduce_max_sync(0xFFFFFFFFu, c2); // max -> min imin
                int lbest = 2047 - (int)l2;
                unsigned gidx = (unsigned)(gbase + lbest);
                unsigned long long key = ((unsigned long long)m2 << 32)
                                       | ((unsigned long long)(8191u - gidx) << 19)
                                       | (unsigned long long)tag;
                if (lane < CSZ) {
                    uint32_t dst = mapa_u32(box_a + (unsigned)(buf * CSZ + rank) * 8u,
                                            (uint32_t)lane);
                    st_cluster_u64(dst, key);   // 4 lanes deliver in parallel
                }
                if (lane == 0) {
                    const uint32_t pa = box_a + (unsigned)(buf * CSZ) * 8u;
                    unsigned long long k0, k1, k2, k3;
                    for (;;) {
                        k0 = ld_vol_u64(pa);
                        k1 = ld_vol_u64(pa + 8u);
                        k2 = ld_vol_u64(pa + 16u);
                        k3 = ld_vol_u64(pa + 24u);
                        if (((unsigned)k0 & TAGM) == tag && ((unsigned)k1 & TAGM) == tag &&
                            ((unsigned)k2 & TAGM) == tag && ((unsigned)k3 & TAGM) == tag)
                            break;
                    }
                    unsigned long long bk = k0;
                    if (k1 > bk) bk = k1;
                    if (k2 > bk) bk = k2;
                    if (k3 > bk) bk = k3;
                    int widx = 8191 - (int)((bk >> 19) & 0x1FFFull);
                    s_cur = widx;
                    if (rank == 0) s_idx[t] = widx;
                }
            }
            __syncthreads();
            int cur = s_cur;
            float4 c = s_pts4[cur];           // single LDS.128 coord fetch
            // publish center t AFTER the barrier, from warp 2 — off warp0's path
            if (rank == 0 && tid == 64) {
                __stcg(&g_center4[b * NGRP + t],
                       make_float4(c.x, c.y, c.z, __int_as_float(t + 1)));
            }
            cx = c.x; cy = c.y; cz = c.z;
        }

        if (rank == 0 && tid < NGRP) {
            int idx = s_idx[tid];
            int go = b * NGRP + tid;
            float4 c = s_pts4[idx];
            out[CENTER_OFF + go * 3 + 0] = c.x;
            out[CENTER_OFF + go * 3 + 1] = c.y;
            out[CENTER_OFF + go * 3 + 2] = c.z;
            const float* ap = base + idx * 6 + 3;
            out[CATTR_OFF + go * 3 + 0] = __ldg(ap + 0);
            out[CATTR_OFF + go * 3 + 1] = __ldg(ap + 1);
            out[CATTR_OFF + go * 3 + 2] = __ldg(ap + 2);
        }
        asm volatile("barrier.cluster.arrive.aligned;" ::: "memory");
        asm volatile("barrier.cluster.wait.aligned;" ::: "memory");

    } else {
        // ================= knn worker path (proven R14/R16 body) ===========
        // wait once for all 32 per-rank g_pts flags (direct writer->reader order)
        if (tid < BATCH * CSZ) {
            while (*(volatile unsigned*)&g_ready[tid] == 0u) __nanosleep(512);
        }
        __threadfence();
        __syncthreads();

        const int w = bid - NFPS;
        for (int task = w; task < BATCH * NGRP; task += NWORK) {
            const int g = task >> 3;       // group index 0..511 (ascending per worker)
            const int b = task & 7;        // batch
            const int bg = b * NGRP + g;

            if (tid == 0) {
                float4 c;
                for (;;) {
                    c = __ldcv(&g_center4[bg]);
                    if (__float_as_int(c.w) == g + 1) break;
                    __nanosleep(256);
                }
                s_c[0] = c.x; s_c[1] = c.y; s_c[2] = c.z;
                s_c[3] = __fadd_rn(__fadd_rn(__fmul_rn(c.x, c.x), __fmul_rn(c.y, c.y)),
                                   __fmul_rn(c.z, c.z));
                s_cnt = 0;
            }
            __syncthreads();
            const float cx = s_c[0], cy = s_c[1], cz = s_c[2], cn = s_c[3];
            const float4* pts = g_pts + (size_t)b * NPTS;   // plain loads (no __ldg)

            unsigned keys[16];
            unsigned long long mn = ~0ull;
#pragma unroll
            for (int k = 0; k < 16; k++) {
                int p = tid + (k << 9);
                float4 q = pts[p];
                float dt = __fmaf_rn(cz, q.z, __fmaf_rn(cy, q.y, __fmul_rn(cx, q.x)));
                float d2 = __fadd_rn(__fsub_rn(cn, __fmul_rn(2.0f, dt)), q.w);
                unsigned u = __float_as_uint(d2);
                unsigned key = u ^ ((unsigned)((int)u >> 31) | 0x80000000u);
                keys[k] = key;
                unsigned long long pk = ((unsigned long long)key << 32) | (unsigned)p;
                if (pk < mn) mn = pk;
            }
            s_min[tid] = mn;
            __syncthreads();

            if (tid < 64) {
                unsigned long long a = s_min[8 * tid];
#pragma unroll
                for (int i = 1; i < 8; i++) {
                    unsigned long long v = s_min[8 * tid + i];
                    if (v < a) a = v;
                }
                s_src[tid] = a;
            }
            __syncthreads();
            if (tid < 64) {
                unsigned long long m = s_src[tid];
                int r = 0;
                for (int j = 0; j < 64; j++) r += (s_src[j] < m) ? 1 : 0;
                if (r == 31) s_T = m;
            }
            __syncthreads();
            const unsigned long long T = s_T;

#pragma unroll
            for (int k = 0; k < 16; k++) {
                unsigned long long pk =
                    ((unsigned long long)keys[k] << 32) | (unsigned)(tid + (k << 9));
                if (pk <= T) {
                    int pos = atomicAdd(&s_cnt, 1);
                    if (pos < CAP) s_cand[pos] = pk;
                }
            }
            __syncthreads();

            int n = s_cnt;
            if (n > CAP) n = CAP;
            for (int c = tid; c < n; c += 512) {
                unsigned long long pk = s_cand[c];
                int r = 0;
                for (int j = 0; j < n; j++) r += (s_cand[j] < pk) ? 1 : 0;
                if (r < KNN) {
                    int p = (int)(pk & 0xFFFFFFFFull);
                    const float* pp = xyz + ((size_t)b * NPTS + p) * 6;
                    size_t o = ((size_t)bg * KNN + r) * 3;
                    out[o + 0] = __fsub_rn(__ldg(pp + 0), cx);
                    out[o + 1] = __fsub_rn(__ldg(pp + 1), cy);
                    out[o + 2] = __fsub_rn(__ldg(pp + 2), cz);
                    out[NEIGH_ATTR_OFF + o + 0] = __ldg(pp + 3);
                    out[NEIGH_ATTR_OFF + o + 1] = __ldg(pp + 4);
                    out[NEIGH_ATTR_OFF + o + 2] = __ldg(pp + 5);
                }
            }
            __syncthreads();   // s_cand/s_cnt reuse next task
        }
    }
}

extern "C" void kernel_launch(void* const* d_in, const int* in_sizes, int n_in,
                              void* d_out, int out_size) {
    const float* xyz = (const float*)d_in[0];
    float* out = (float*)d_out;
    (void)in_sizes; (void)n_in; (void)out_size;

    const int smem = NPTS * (int)sizeof(float4);   // 128 KB float4 coord plane
    cudaFuncSetAttribute(fused_kernel, cudaFuncAttributeMaxDynamicSharedMemorySize, smem);
    fused_kernel<<<NCTA, 512, smem>>>(xyz, out);
}